// round 4
// baseline (speedup 1.0000x reference)
#include <cuda_runtime.h>
#include <stdint.h>

// Problem constants
#define NBINS      32
#define NCH        64            // B*C = 8*8
#define HW         65536         // 256*256 pixels per channel
#define NSUB       1024          // fine histogram sub-bins over [0,1)
#define CTAS_PER_CH 16
#define NCTA       (NCH * CTAS_PER_CH)        // 1024
#define F4_PER_CTA ((HW / 4) / CTAS_PER_CH)   // 1024 float4 per CTA
#define PAD        160           // +-5 sigma = +-160 sub-bins
#define WIN        (2 * PAD)     // 320
#define NSTEP      (WIN / 32)    // 10 strided warp steps

#define AMPL   0.3989472f        // ER/RATIO = 1/2.5066
#define INV31  (1.0f / 31.0f)    // bin spacing (linspace(0,1,32))
#define K512   512.0f            // 1/(2*sigma^2), sigma = 1/32
#define DELTA  (1.0f / 1024.0f)  // sub-bin width
#define STEP32 (32.0f * DELTA)   // lane stride in x (= 1 sigma)

// Cross-CTA ordering state for in-kernel output zeroing.
// Zero-initialized at load; the LAST finishing CTA resets both each launch,
// so every graph replay starts from {0, 0}. No residency assumptions.
__device__ unsigned int g_flag;   // 1 once out[] is zeroed by CTA 0
__device__ unsigned int g_done;   // CTAs that have passed the flag wait

// ---------------------------------------------------------------------------
// Single fused kernel, one CTA per slab (1/16 channel):
//   Phase 0 (CTA 0 only): zero out[2048], fence, publish flag.
//   Phase 1: fine 1024-bin count histogram of own 4096 pixels (shared atomics).
//   Phase 2: counts -> +-PAD zero-padded float array in shared.
//   Phase 3: warp-per-bin Gaussian window: 32 consecutive lanes (conflict-free
//            LDS), 10 steps of 32 sub-bins, lattice recurrence
//            (w *= r; r *= exp(-1)) -> 2 expf per (bin,lane).
//   Phase 4: wait for flag, then 32 atomicAdds of per-slab partials into out.
// ---------------------------------------------------------------------------
__global__ __launch_bounds__(256, 8)
void fused_kernel(const float* __restrict__ x, float* __restrict__ out)
{
    __shared__ unsigned int hc[NSUB];        // 4 KB counts
    __shared__ float        hf[NSUB + WIN];  // 5.25 KB padded floats
    __shared__ float        s_part[NBINS];   // per-slab partial results

    const int tid = threadIdx.x;

    // ---- Phase 0: CTA 0 zeroes the output and publishes the flag ----------
    if (blockIdx.x == 0) {
        #pragma unroll
        for (int i = tid; i < NCH * NBINS; i += 256) out[i] = 0.0f;
        __threadfence();
        if (tid == 0) atomicExch(&g_flag, 1u);
    }

    #pragma unroll
    for (int i = tid; i < NSUB; i += 256) hc[i] = 0u;
    __syncthreads();

    // ---- Phase 1: histogram own slice -------------------------------------
    const float4* __restrict__ p =
        reinterpret_cast<const float4*>(x) + (size_t)blockIdx.x * F4_PER_CTA;

    #pragma unroll
    for (int i = tid; i < F4_PER_CTA; i += 256) {
        float4 v = p[i];
        int b0 = (int)(v.x * (float)NSUB);
        int b1 = (int)(v.y * (float)NSUB);
        int b2 = (int)(v.z * (float)NSUB);
        int b3 = (int)(v.w * (float)NSUB);
        b0 = min(NSUB - 1, max(0, b0));
        b1 = min(NSUB - 1, max(0, b1));
        b2 = min(NSUB - 1, max(0, b2));
        b3 = min(NSUB - 1, max(0, b3));
        atomicAdd(&hc[b0], 1u);
        atomicAdd(&hc[b1], 1u);
        atomicAdd(&hc[b2], 1u);
        atomicAdd(&hc[b3], 1u);
    }
    __syncthreads();

    // ---- Phase 2: counts -> padded floats ---------------------------------
    #pragma unroll
    for (int i = tid; i < NSUB; i += 256) hf[PAD + i] = (float)hc[i];
    #pragma unroll
    for (int i = tid; i < PAD; i += 256) {
        hf[i] = 0.0f;
        hf[PAD + NSUB + i] = 0.0f;
    }
    __syncthreads();

    // ---- Phase 3: warp-per-bin convolution --------------------------------
    const int warp = tid >> 5;
    const int lane = tid & 31;
    const float gS = __expf(-2.0f * K512 * STEP32 * STEP32);  // exp(-1)

    #pragma unroll
    for (int b = 0; b < 4; b++) {
        const int j = warp + 8 * b;                 // bin 0..31
        const float cj = (float)j * INV31;
        const int icenter = (int)(cj * (float)NSUB);
        const float d0 = ((float)(icenter - PAD + lane) + 0.5f) * DELTA - cj;

        float w = __expf(-d0 * d0 * K512);
        float r = __expf(-K512 * STEP32 * (2.0f * d0 + STEP32));

        int idx = icenter + lane;                   // = PAD + m0 + lane
        float acc = 0.0f;
        #pragma unroll
        for (int i = 0; i < NSTEP; i++) {
            acc = fmaf(hf[idx], w, acc);
            w *= r;
            r *= gS;
            idx += 32;
        }

        #pragma unroll
        for (int off = 16; off > 0; off >>= 1)
            acc += __shfl_down_sync(0xFFFFFFFFu, acc, off);

        if (lane == 0) s_part[j] = acc * AMPL;
    }
    __syncthreads();

    // ---- Phase 4: wait for zeroed output, then accumulate -----------------
    if (tid == 0) {
        while (atomicAdd(&g_flag, 0u) == 0u) { }
    }
    __syncthreads();
    __threadfence();   // acquire: order out-zero stores before our RMWs

    const int ch = blockIdx.x >> 4;   // 16 slabs per channel
    if (tid < NBINS)
        atomicAdd(&out[ch * NBINS + tid], s_part[tid]);

    __syncthreads();
    if (tid == 0) {
        // Last CTA to finish resets the cross-launch state for the next replay.
        unsigned int d = atomicAdd(&g_done, 1u);
        if (d == (unsigned int)(gridDim.x - 1)) {
            atomicExch(&g_flag, 0u);
            atomicExch(&g_done, 0u);
        }
    }
}

// ---------------------------------------------------------------------------
extern "C" void kernel_launch(void* const* d_in, const int* in_sizes, int n_in,
                              void* d_out, int out_size)
{
    const float* x = (const float*)d_in[0];   // [8,8,256,256] fp32
    float* out = (float*)d_out;               // [8,256,1,1] = 2048 fp32

    fused_kernel<<<NCTA, 256>>>(x, out);
}

// round 5
// speedup vs baseline: 1.0175x; 1.0175x over previous
#include <cuda_runtime.h>
#include <stdint.h>

// Problem constants
#define NBINS      32
#define NCH        64            // B*C = 8*8
#define HW         65536         // 256*256 pixels per channel
#define NSUB       1024          // fine histogram sub-bins over [0,1)
#define CTAS_PER_CH 16
#define NCTA       (NCH * CTAS_PER_CH)        // 1024
#define F4_PER_CTA ((HW / 4) / CTAS_PER_CH)   // 1024 float4 per CTA
#define PAD        160           // +-5 sigma = +-160 sub-bins
#define WIN        (2 * PAD)     // 320
#define NSTEP      (WIN / 32)    // 10 strided warp steps

#define AMPL   0.3989472f        // ER/RATIO = 1/2.5066
#define INV31  (1.0f / 31.0f)    // bin spacing (linspace(0,1,32))
#define K512   512.0f            // 1/(2*sigma^2), sigma = 1/32
#define DELTA  (1.0f / 1024.0f)  // sub-bin width
#define STEP32 (32.0f * DELTA)   // lane stride in x (= 1 sigma)

// Per-slab partial results (plain stores, fully overwritten every launch).
__device__ float        g_part[NCTA * NBINS];     // 128 KB
// Per-channel completion counters (64 distinct addresses -> no hot spot).
// Zero at load; the reducing CTA resets its own counter -> replay-safe.
__device__ unsigned int g_cnt[NCH];

// ---------------------------------------------------------------------------
// Single fused kernel, one CTA per slab (1/16 channel):
//   Phase 1: fine 1024-bin count histogram of own 4096 pixels (shared atomics).
//   Phase 2: counts -> +-PAD zero-padded float array in shared.
//   Phase 3: warp-per-bin Gaussian window: 32 consecutive lanes (conflict-free
//            LDS), 10 steps of 32 sub-bins, lattice recurrence -> 2 expf each.
//   Phase 4: store 32-float partial to private slab, fence, bump channel
//            counter; the LAST slab of each channel sums all 16 partials and
//            writes out[ch*32..] directly (no zeroing, no output atomics).
// ---------------------------------------------------------------------------
__global__ __launch_bounds__(256, 8)
void fused_kernel(const float* __restrict__ x, float* __restrict__ out)
{
    __shared__ unsigned int hc[NSUB];        // 4 KB counts
    __shared__ float        hf[NSUB + WIN];  // 5.25 KB padded floats
    __shared__ float        s_part[NBINS];
    __shared__ unsigned int s_last;

    const int tid = threadIdx.x;

    #pragma unroll
    for (int i = tid; i < NSUB; i += 256) hc[i] = 0u;
    __syncthreads();

    // ---- Phase 1: histogram own slice -------------------------------------
    const float4* __restrict__ p =
        reinterpret_cast<const float4*>(x) + (size_t)blockIdx.x * F4_PER_CTA;

    #pragma unroll
    for (int i = tid; i < F4_PER_CTA; i += 256) {
        float4 v = p[i];
        int b0 = (int)(v.x * (float)NSUB);
        int b1 = (int)(v.y * (float)NSUB);
        int b2 = (int)(v.z * (float)NSUB);
        int b3 = (int)(v.w * (float)NSUB);
        b0 = min(NSUB - 1, max(0, b0));
        b1 = min(NSUB - 1, max(0, b1));
        b2 = min(NSUB - 1, max(0, b2));
        b3 = min(NSUB - 1, max(0, b3));
        atomicAdd(&hc[b0], 1u);
        atomicAdd(&hc[b1], 1u);
        atomicAdd(&hc[b2], 1u);
        atomicAdd(&hc[b3], 1u);
    }
    __syncthreads();

    // ---- Phase 2: counts -> padded floats ---------------------------------
    #pragma unroll
    for (int i = tid; i < NSUB; i += 256) hf[PAD + i] = (float)hc[i];
    #pragma unroll
    for (int i = tid; i < PAD; i += 256) {
        hf[i] = 0.0f;
        hf[PAD + NSUB + i] = 0.0f;
    }
    __syncthreads();

    // ---- Phase 3: warp-per-bin convolution --------------------------------
    const int warp = tid >> 5;
    const int lane = tid & 31;
    const float gS = __expf(-2.0f * K512 * STEP32 * STEP32);  // exp(-1)

    #pragma unroll
    for (int b = 0; b < 4; b++) {
        const int j = warp + 8 * b;                 // bin 0..31
        const float cj = (float)j * INV31;
        const int icenter = (int)(cj * (float)NSUB);
        const float d0 = ((float)(icenter - PAD + lane) + 0.5f) * DELTA - cj;

        float w = __expf(-d0 * d0 * K512);
        float r = __expf(-K512 * STEP32 * (2.0f * d0 + STEP32));

        int idx = icenter + lane;                   // = PAD + m0 + lane
        float acc = 0.0f;
        #pragma unroll
        for (int i = 0; i < NSTEP; i++) {
            acc = fmaf(hf[idx], w, acc);
            w *= r;
            r *= gS;
            idx += 32;
        }

        #pragma unroll
        for (int off = 16; off > 0; off >>= 1)
            acc += __shfl_down_sync(0xFFFFFFFFu, acc, off);

        if (lane == 0) s_part[j] = acc * AMPL;
    }
    __syncthreads();

    // ---- Phase 4: publish partial; last slab per channel reduces ----------
    const int ch = blockIdx.x >> 4;   // 16 slabs per channel

    if (tid < NBINS)
        g_part[blockIdx.x * NBINS + tid] = s_part[tid];
    __threadfence();
    __syncthreads();                  // all 32 stores issued+fenced

    if (tid == 0) {
        unsigned int old = atomicAdd(&g_cnt[ch], 1u);
        s_last = (old == CTAS_PER_CH - 1) ? 1u : 0u;
    }
    __syncthreads();

    if (s_last) {
        __threadfence();              // order: peers' stores visible before loads
        if (tid < NBINS) {
            const float* __restrict__ base = g_part + (size_t)ch * CTAS_PER_CH * NBINS;
            float acc = 0.0f;
            #pragma unroll
            for (int k = 0; k < CTAS_PER_CH; k++)
                acc += base[k * NBINS + tid];
            out[ch * NBINS + tid] = acc;
        }
        if (tid == 0)
            atomicExch(&g_cnt[ch], 0u);   // reset for next graph replay
    }
}

// ---------------------------------------------------------------------------
extern "C" void kernel_launch(void* const* d_in, const int* in_sizes, int n_in,
                              void* d_out, int out_size)
{
    const float* x = (const float*)d_in[0];   // [8,8,256,256] fp32
    float* out = (float*)d_out;               // [8,256,1,1] = 2048 fp32

    fused_kernel<<<NCTA, 256>>>(x, out);
}